// round 1
// baseline (speedup 1.0000x reference)
#include <cuda_runtime.h>
#include <cuda_bf16.h>

// Problem constants
#define B_   4
#define S_   2048
#define D_   1024
#define H_   16
#define DK_  64
#define M_   (B_ * S_)   // 8192 rows for all projection GEMMs

// Scratch (device globals — no allocations allowed)
__device__ float g_Q[(size_t)M_ * D_];
__device__ float g_K[(size_t)M_ * D_];
__device__ float g_V[(size_t)M_ * D_];
__device__ float g_O[(size_t)M_ * D_];

// ---------------------------------------------------------------------------
// SGEMM with fused bias: C[M,N] = A[M,K] @ W[K,N] + bias[N]
// 128x128 block tile, BK=8, 256 threads, 8x8 per-thread micro-tile.
// M % 128 == 0, N % 128 == 0, K % 8 == 0 (all true here: 8192/1024/1024).
// ---------------------------------------------------------------------------
__global__ __launch_bounds__(256, 2)
void sgemm_bias(const float* __restrict__ A, const float* __restrict__ W,
                const float* __restrict__ bias, float* __restrict__ C,
                int M, int N, int K)
{
    constexpr int BM = 128, BN = 128, BK = 8;
    __shared__ float As[BK][BM];   // transposed A tile
    __shared__ float Bs[BK][BN];

    const int tid  = threadIdx.x;
    const int brow = blockIdx.y;
    const int bcol = blockIdx.x;

    // global-load assignments (float4)
    const int arow = tid >> 1;            // 0..127
    const int acol = (tid & 1) * 4;       // 0 or 4
    const int brw  = tid >> 5;            // 0..7
    const int bcl  = (tid & 31) * 4;      // 0..124

    // compute assignments
    const int ty = tid >> 4;              // 0..15
    const int tx = tid & 15;              // 0..15

    const float* Aptr = A + (size_t)(brow * BM + arow) * K + acol;
    const float* Wptr = W + (size_t)brw * N + (size_t)bcol * BN + bcl;

    float acc[8][8];
#pragma unroll
    for (int i = 0; i < 8; i++)
#pragma unroll
        for (int j = 0; j < 8; j++) acc[i][j] = 0.0f;

    for (int kt = 0; kt < K; kt += BK) {
        float4 av = *(const float4*)(Aptr + kt);
        As[acol + 0][arow] = av.x;
        As[acol + 1][arow] = av.y;
        As[acol + 2][arow] = av.z;
        As[acol + 3][arow] = av.w;
        float4 bv = *(const float4*)(Wptr + (size_t)kt * N);
        *(float4*)&Bs[brw][bcl] = bv;
        __syncthreads();

#pragma unroll
        for (int k = 0; k < BK; k++) {
            float ra[8], rb[8];
            *(float4*)&ra[0] = *(const float4*)&As[k][ty * 8];
            *(float4*)&ra[4] = *(const float4*)&As[k][ty * 8 + 4];
            *(float4*)&rb[0] = *(const float4*)&Bs[k][tx * 8];
            *(float4*)&rb[4] = *(const float4*)&Bs[k][tx * 8 + 4];
#pragma unroll
            for (int i = 0; i < 8; i++)
#pragma unroll
                for (int j = 0; j < 8; j++)
                    acc[i][j] += ra[i] * rb[j];
        }
        __syncthreads();
    }

    // epilogue with fused bias
    float bvals[8];
#pragma unroll
    for (int j = 0; j < 8; j++) bvals[j] = bias[bcol * BN + tx * 8 + j];

#pragma unroll
    for (int i = 0; i < 8; i++) {
        float* Crow = C + (size_t)(brow * BM + ty * 8 + i) * N + bcol * BN + tx * 8;
        float4 o0, o1;
        o0.x = acc[i][0] + bvals[0]; o0.y = acc[i][1] + bvals[1];
        o0.z = acc[i][2] + bvals[2]; o0.w = acc[i][3] + bvals[3];
        o1.x = acc[i][4] + bvals[4]; o1.y = acc[i][5] + bvals[5];
        o1.z = acc[i][6] + bvals[6]; o1.w = acc[i][7] + bvals[7];
        *(float4*)(Crow)     = o0;
        *(float4*)(Crow + 4) = o1;
    }
}

// ---------------------------------------------------------------------------
// Flash attention: one CTA per (64 q-rows, head, batch).
// Q/K/V layout: [b, s, D] with head h occupying columns [h*64, h*64+64).
// Online softmax; 4x4 micro-tiles for both GEMMs; 256 threads.
// Dynamic smem: Qs/Ks/Vs/Ps at 64x65 + m/l/corr rows = 67,328 bytes.
// ---------------------------------------------------------------------------
__global__ __launch_bounds__(256, 3)
void attn_kernel(const float* __restrict__ Q, const float* __restrict__ K,
                 const float* __restrict__ V, float* __restrict__ O)
{
    extern __shared__ float sm[];
    float* Qs   = sm;                    // 64*65
    float* Ks   = Qs + 64 * 65;
    float* Vs   = Ks + 64 * 65;
    float* Ps   = Vs + 64 * 65;
    float* m_sh = Ps + 64 * 65;          // 64
    float* l_sh = m_sh + 64;             // 64
    float* c_sh = l_sh + 64;             // 64

    const int tid = threadIdx.x;
    const int qt  = blockIdx.x;          // q tile (0..31)
    const int h   = blockIdx.y;          // head
    const int b   = blockIdx.z;          // batch
    const int q0  = qt * 64;

    const size_t headOff = (size_t)h * DK_;
    const float* Qb = Q + ((size_t)b * S_ + q0) * D_ + headOff;
    const float* Kb = K + (size_t)b * S_ * D_ + headOff;
    const float* Vb = V + (size_t)b * S_ * D_ + headOff;

    // load Q tile (64 x 64)
#pragma unroll
    for (int i = 0; i < 16; i++) {
        int lin = tid + i * 256;
        int r = lin >> 6, c = lin & 63;
        Qs[r * 65 + c] = Qb[(size_t)r * D_ + c];
    }
    if (tid < 64) { m_sh[tid] = -3.0e38f; l_sh[tid] = 0.0f; }

    const int ty = tid >> 4, tx = tid & 15;
    float oacc[4][4];
#pragma unroll
    for (int ii = 0; ii < 4; ii++)
#pragma unroll
        for (int jj = 0; jj < 4; jj++) oacc[ii][jj] = 0.0f;

    for (int jt = 0; jt < S_; jt += 64) {
        __syncthreads();   // protects Qs (1st iter) and Ks/Vs/Ps reuse

        // load K,V tiles (64 x 64 each)
#pragma unroll
        for (int i = 0; i < 16; i++) {
            int lin = tid + i * 256;
            int r = lin >> 6, c = lin & 63;
            Ks[r * 65 + c] = Kb[(size_t)(jt + r) * D_ + c];
            Vs[r * 65 + c] = Vb[(size_t)(jt + r) * D_ + c];
        }
        __syncthreads();

        // S = Q @ K^T (scaled)
        float sreg[4][4];
#pragma unroll
        for (int ii = 0; ii < 4; ii++)
#pragma unroll
            for (int jj = 0; jj < 4; jj++) sreg[ii][jj] = 0.0f;

#pragma unroll 8
        for (int d = 0; d < 64; d++) {
            float qv[4], kv[4];
#pragma unroll
            for (int ii = 0; ii < 4; ii++) qv[ii] = Qs[(ty * 4 + ii) * 65 + d];
#pragma unroll
            for (int jj = 0; jj < 4; jj++) kv[jj] = Ks[(tx * 4 + jj) * 65 + d];
#pragma unroll
            for (int ii = 0; ii < 4; ii++)
#pragma unroll
                for (int jj = 0; jj < 4; jj++)
                    sreg[ii][jj] += qv[ii] * kv[jj];
        }

#pragma unroll
        for (int ii = 0; ii < 4; ii++)
#pragma unroll
            for (int jj = 0; jj < 4; jj++)
                Ps[(ty * 4 + ii) * 65 + tx * 4 + jj] = sreg[ii][jj] * 0.125f;
        __syncthreads();

        // online softmax per row (64 threads, one row each; conflict-free: bank = (r+j)%32)
        if (tid < 64) {
            const int r = tid;
            float mold = m_sh[r];
            float mnew = mold;
#pragma unroll 8
            for (int j = 0; j < 64; j++) mnew = fmaxf(mnew, Ps[r * 65 + j]);
            float corr = __expf(mold - mnew);
            float ls = 0.0f;
#pragma unroll 8
            for (int j = 0; j < 64; j++) {
                float e = __expf(Ps[r * 65 + j] - mnew);
                Ps[r * 65 + j] = e;
                ls += e;
            }
            l_sh[r] = l_sh[r] * corr + ls;
            m_sh[r] = mnew;
            c_sh[r] = corr;
        }
        __syncthreads();

        // rescale accumulators, then O += P @ V
        float cr[4];
#pragma unroll
        for (int ii = 0; ii < 4; ii++) cr[ii] = c_sh[ty * 4 + ii];
#pragma unroll
        for (int ii = 0; ii < 4; ii++)
#pragma unroll
            for (int jj = 0; jj < 4; jj++) oacc[ii][jj] *= cr[ii];

#pragma unroll 8
        for (int j = 0; j < 64; j++) {
            float pv[4], vv[4];
#pragma unroll
            for (int ii = 0; ii < 4; ii++) pv[ii] = Ps[(ty * 4 + ii) * 65 + j];
#pragma unroll
            for (int jj = 0; jj < 4; jj++) vv[jj] = Vs[j * 65 + tx * 4 + jj];
#pragma unroll
            for (int ii = 0; ii < 4; ii++)
#pragma unroll
                for (int jj = 0; jj < 4; jj++)
                    oacc[ii][jj] += pv[ii] * vv[jj];
        }
    }

    // final normalize + store (no further writes to l_sh after last softmax sync)
    float* Ob = O + ((size_t)b * S_ + q0) * D_ + headOff;
#pragma unroll
    for (int ii = 0; ii < 4; ii++) {
        float inv = 1.0f / l_sh[ty * 4 + ii];
#pragma unroll
        for (int jj = 0; jj < 4; jj++)
            Ob[(size_t)(ty * 4 + ii) * D_ + tx * 4 + jj] = oacc[ii][jj] * inv;
    }
}

// ---------------------------------------------------------------------------
// kernel_launch: q,k,v projections -> flash attention -> output projection.
// Inputs (metadata order): q,k,v,wq,bq,wk,bk,wv,bv,wo,bo
// ---------------------------------------------------------------------------
extern "C" void kernel_launch(void* const* d_in, const int* in_sizes, int n_in,
                              void* d_out, int out_size)
{
    const float* q  = (const float*)d_in[0];
    const float* k  = (const float*)d_in[1];
    const float* v  = (const float*)d_in[2];
    const float* wq = (const float*)d_in[3];
    const float* bq = (const float*)d_in[4];
    const float* wk = (const float*)d_in[5];
    const float* bk = (const float*)d_in[6];
    const float* wv = (const float*)d_in[7];
    const float* bv = (const float*)d_in[8];
    const float* wo = (const float*)d_in[9];
    const float* bo = (const float*)d_in[10];
    float* out = (float*)d_out;

    float *gQ, *gK, *gV, *gO;
    cudaGetSymbolAddress((void**)&gQ, g_Q);
    cudaGetSymbolAddress((void**)&gK, g_K);
    cudaGetSymbolAddress((void**)&gV, g_V);
    cudaGetSymbolAddress((void**)&gO, g_O);

    dim3 ggrid(D_ / 128, M_ / 128);   // (8, 64)

    sgemm_bias<<<ggrid, 256>>>(q, wq, bq, gQ, M_, D_, D_);
    sgemm_bias<<<ggrid, 256>>>(k, wk, bk, gK, M_, D_, D_);
    sgemm_bias<<<ggrid, 256>>>(v, wv, bv, gV, M_, D_, D_);

    size_t smem = (size_t)(4 * 64 * 65 + 3 * 64) * sizeof(float);  // 67,328 B
    cudaFuncSetAttribute(attn_kernel, cudaFuncAttributeMaxDynamicSharedMemorySize,
                         (int)smem);
    attn_kernel<<<dim3(S_ / 64, H_, B_), 256, smem>>>(gQ, gK, gV, gO);

    sgemm_bias<<<ggrid, 256>>>(gO, wo, bo, out, M_, D_, D_);
}

// round 3
// speedup vs baseline: 1.3240x; 1.3240x over previous
#include <cuda_runtime.h>
#include <cuda_bf16.h>
#include <cstdint>

// Problem constants
#define B_   4
#define S_   2048
#define D_   1024
#define H_   16
#define DK_  64
#define M_   (B_ * S_)   // 8192

// ---------------------------------------------------------------------------
// Scratch (device globals — no allocations allowed)
// ---------------------------------------------------------------------------
__device__ float g_Q[(size_t)M_ * D_];
__device__ float g_K[(size_t)M_ * D_];
__device__ float g_V[(size_t)M_ * D_];
__device__ float g_O[(size_t)M_ * D_];
__device__ __nv_bfloat16 g_Ahi[(size_t)M_ * D_];
__device__ __nv_bfloat16 g_Alo[(size_t)M_ * D_];
__device__ __nv_bfloat16 g_Whi[(size_t)D_ * D_];   // transposed: [N, K]
__device__ __nv_bfloat16 g_Wlo[(size_t)D_ * D_];

// ---------------------------------------------------------------------------
// Helpers (base-target PTX only: ldmatrix / mma.sync / cp.async — no tcgen05)
// ---------------------------------------------------------------------------
__device__ __forceinline__ uint32_t smem_to_u32(const void* p) {
    uint32_t a;
    asm("{ .reg .u64 t; cvta.to.shared.u64 t, %1; cvt.u32.u64 %0, t; }"
        : "=r"(a) : "l"(p));
    return a;
}

__device__ __forceinline__ void ldsm_x4(uint32_t* r, uint32_t addr) {
    asm volatile("ldmatrix.sync.aligned.m8n8.x4.shared.b16 {%0,%1,%2,%3}, [%4];"
        : "=r"(r[0]), "=r"(r[1]), "=r"(r[2]), "=r"(r[3]) : "r"(addr));
}

__device__ __forceinline__ void mma_bf16(float* c, const uint32_t* a,
                                         uint32_t b0, uint32_t b1) {
    asm volatile(
        "mma.sync.aligned.m16n8k16.row.col.f32.bf16.bf16.f32 "
        "{%0,%1,%2,%3}, {%4,%5,%6,%7}, {%8,%9}, {%0,%1,%2,%3};"
        : "+f"(c[0]), "+f"(c[1]), "+f"(c[2]), "+f"(c[3])
        : "r"(a[0]), "r"(a[1]), "r"(a[2]), "r"(a[3]), "r"(b0), "r"(b1));
}

__device__ __forceinline__ void cp16(uint32_t dst, const void* src) {
    asm volatile("cp.async.cg.shared.global [%0], [%1], 16;\n"
        :: "r"(dst), "l"(src));
}
__device__ __forceinline__ void cp_commit() {
    asm volatile("cp.async.commit_group;\n" ::: "memory");
}

// ---------------------------------------------------------------------------
// bf16 split kernels
// ---------------------------------------------------------------------------
__global__ void split_kernel(const float* __restrict__ x,
                             __nv_bfloat16* __restrict__ hi,
                             __nv_bfloat16* __restrict__ lo, int n4)
{
    int i = blockIdx.x * blockDim.x + threadIdx.x;
    if (i >= n4) return;
    float4 v = ((const float4*)x)[i];
    __nv_bfloat16 h0 = __float2bfloat16(v.x);
    __nv_bfloat16 h1 = __float2bfloat16(v.y);
    __nv_bfloat16 h2 = __float2bfloat16(v.z);
    __nv_bfloat16 h3 = __float2bfloat16(v.w);
    __nv_bfloat16 l0 = __float2bfloat16(v.x - __bfloat162float(h0));
    __nv_bfloat16 l1 = __float2bfloat16(v.y - __bfloat162float(h1));
    __nv_bfloat16 l2 = __float2bfloat16(v.z - __bfloat162float(h2));
    __nv_bfloat16 l3 = __float2bfloat16(v.w - __bfloat162float(h3));
    __nv_bfloat162* hp = (__nv_bfloat162*)(hi + (size_t)i * 4);
    __nv_bfloat162* lp = (__nv_bfloat162*)(lo + (size_t)i * 4);
    hp[0] = __halves2bfloat162(h0, h1);
    hp[1] = __halves2bfloat162(h2, h3);
    lp[0] = __halves2bfloat162(l0, l1);
    lp[1] = __halves2bfloat162(l2, l3);
}

// W [K=1024, N=1024] row-major -> Wt hi/lo [N, K] row-major bf16
__global__ void transpose_split_kernel(const float* __restrict__ w,
                                       __nv_bfloat16* __restrict__ hi,
                                       __nv_bfloat16* __restrict__ lo)
{
    __shared__ float t[32][33];
    int tx = threadIdx.x, ty = threadIdx.y;         // 32 x 8
    int bx = blockIdx.x * 32, by = blockIdx.y * 32; // bx: n, by: k
#pragma unroll
    for (int i = 0; i < 4; i++)
        t[ty + i * 8][tx] = w[(size_t)(by + ty + i * 8) * D_ + bx + tx];
    __syncthreads();
#pragma unroll
    for (int i = 0; i < 4; i++) {
        float v = t[tx][ty + i * 8];   // = w[by+tx][bx+ty+i*8]
        __nv_bfloat16 h = __float2bfloat16(v);
        __nv_bfloat16 l = __float2bfloat16(v - __bfloat162float(h));
        size_t o = (size_t)(bx + ty + i * 8) * D_ + by + tx;
        hi[o] = h;
        lo[o] = l;
    }
}

// ---------------------------------------------------------------------------
// HMMA bf16-split GEMM: C[M,1024] = (Ahi+Alo) @ (Bhi+Blo)^T + bias
// A: [M,K] row-major bf16; B: [N,K] row-major bf16 (pre-transposed W).
// 128x128 tile, BK=32, 8 warps (2x4), warp tile 64x32, m16n8k16 mma,
// cp.async double buffer, XOR-swizzled smem for conflict-free ldmatrix.
// ---------------------------------------------------------------------------
#define BK_        32
#define STAGE_B    32768              // 4 arrays * 128 rows * 64 bytes
#define AH_OFF     0
#define AL_OFF     8192
#define BH_OFF     16384
#define BL_OFF     24576
#define GSMEM      (2 * STAGE_B)      // 65536
#define NSTAGES    (D_ / BK_)         // 32

__device__ __forceinline__ void load_stage(uint32_t smem_u, int buf,
    const __nv_bfloat16* __restrict__ Ah, const __nv_bfloat16* __restrict__ Al,
    const __nv_bfloat16* __restrict__ Bh, const __nv_bfloat16* __restrict__ Bl,
    int m0, int n0, int kt, int tid)
{
    const int row = tid >> 1;            // 0..127
    const int c0  = (tid & 1) * 2;       // chunk base 0 or 2
    const int swr = (row >> 1) & 3;
    const uint32_t sb = smem_u + (uint32_t)buf * STAGE_B;
    const uint32_t rowoff = (uint32_t)row * 64;
    const size_t ga = (size_t)(m0 + row) * D_ + kt;
    const size_t gb = (size_t)(n0 + row) * D_ + kt;
#pragma unroll
    for (int cc = 0; cc < 2; cc++) {
        int c = c0 + cc;
        uint32_t so = rowoff + (uint32_t)((c ^ swr) << 4);
        cp16(sb + AH_OFF + so, Ah + ga + c * 8);
        cp16(sb + AL_OFF + so, Al + ga + c * 8);
        cp16(sb + BH_OFF + so, Bh + gb + c * 8);
        cp16(sb + BL_OFF + so, Bl + gb + c * 8);
    }
}

__global__ __launch_bounds__(256, 1)
void gemm_hmma(const __nv_bfloat16* __restrict__ Ahi,
               const __nv_bfloat16* __restrict__ Alo,
               const __nv_bfloat16* __restrict__ Bhi,
               const __nv_bfloat16* __restrict__ Blo,
               const float* __restrict__ bias, float* __restrict__ C)
{
    extern __shared__ char smem[];
    const uint32_t smem_u = smem_to_u32(smem);
    const int tid = threadIdx.x;
    const int m0 = blockIdx.y * 128, n0 = blockIdx.x * 128;

    const int lane  = tid & 31;
    const int warpM = (tid >> 5) & 1;    // 0..1 -> 64 rows each
    const int warpN = tid >> 6;          // 0..3 -> 32 cols each
    const int q  = lane >> 3, rr = lane & 7;
    const int rbase = rr + (q & 1) * 8;
    const int csel  = q >> 1;

    int arow[4], brow[2];
#pragma unroll
    for (int i = 0; i < 4; i++) arow[i] = warpM * 64 + i * 16 + rbase;
#pragma unroll
    for (int j = 0; j < 2; j++) brow[j] = warpN * 32 + j * 16 + rbase;

    float acc[4][4][4];
#pragma unroll
    for (int i = 0; i < 4; i++)
#pragma unroll
        for (int j = 0; j < 4; j++)
#pragma unroll
            for (int r = 0; r < 4; r++) acc[i][j][r] = 0.0f;

    load_stage(smem_u, 0, Ahi, Alo, Bhi, Blo, m0, n0, 0, tid);
    cp_commit();
    load_stage(smem_u, 1, Ahi, Alo, Bhi, Blo, m0, n0, BK_, tid);
    cp_commit();

    for (int c = 0; c < NSTAGES; c++) {
        if (c < NSTAGES - 1)
            asm volatile("cp.async.wait_group 1;\n" ::: "memory");
        else
            asm volatile("cp.async.wait_group 0;\n" ::: "memory");
        __syncthreads();

        const uint32_t sb = smem_u + (uint32_t)(c & 1) * STAGE_B;
#pragma unroll
        for (int ks = 0; ks < 2; ks++) {
            uint32_t ah[4][4], al[4][4], bh[2][4], bl[2][4];
            const int kc = ks * 2 + csel;
#pragma unroll
            for (int i = 0; i < 4; i++) {
                int r = arow[i];
                uint32_t ad = sb + (uint32_t)(r * 64) +
                              (uint32_t)((kc ^ ((r >> 1) & 3)) << 4);
                ldsm_x4(ah[i], ad + AH_OFF);
                ldsm_x4(al[i], ad + AL_OFF);
            }
#pragma unroll
            for (int j = 0; j < 2; j++) {
                int r = brow[j];
                uint32_t bd = sb + (uint32_t)(r * 64) +
                              (uint32_t)((kc ^ ((r >> 1) & 3)) << 4);
                ldsm_x4(bh[j], bd + BH_OFF);
                ldsm_x4(bl[j], bd + BL_OFF);
            }
#pragma unroll
            for (int i = 0; i < 4; i++)
#pragma unroll
                for (int j = 0; j < 4; j++) {
                    const int j2 = j >> 1, p = j & 1;
                    mma_bf16(acc[i][j], ah[i], bh[j2][p], bh[j2][p + 2]);
                    mma_bf16(acc[i][j], ah[i], bl[j2][p], bl[j2][p + 2]);
                    mma_bf16(acc[i][j], al[i], bh[j2][p], bh[j2][p + 2]);
                }
        }
        __syncthreads();
        if (c + 2 < NSTAGES) {
            load_stage(smem_u, c & 1, Ahi, Alo, Bhi, Blo, m0, n0,
                       (c + 2) * BK_, tid);
            cp_commit();
        }
    }

    // epilogue: fragment-direct stores with fused bias
    const int crow = lane >> 2, ccol = (lane & 3) * 2;
#pragma unroll
    for (int i = 0; i < 4; i++) {
        const int gr = m0 + warpM * 64 + i * 16 + crow;
#pragma unroll
        for (int j = 0; j < 4; j++) {
            const int gc = n0 + warpN * 32 + j * 8 + ccol;
            const float b0 = __ldg(bias + gc), b1 = __ldg(bias + gc + 1);
            float2 v0 = make_float2(acc[i][j][0] + b0, acc[i][j][1] + b1);
            float2 v1 = make_float2(acc[i][j][2] + b0, acc[i][j][3] + b1);
            *(float2*)(C + (size_t)gr * D_ + gc)       = v0;
            *(float2*)(C + (size_t)(gr + 8) * D_ + gc) = v1;
        }
    }
}

// ---------------------------------------------------------------------------
// Flash attention (UNCHANGED from round 0 — known correct)
// ---------------------------------------------------------------------------
__global__ __launch_bounds__(256, 3)
void attn_kernel(const float* __restrict__ Q, const float* __restrict__ K,
                 const float* __restrict__ V, float* __restrict__ O)
{
    extern __shared__ float sm[];
    float* Qs   = sm;
    float* Ks   = Qs + 64 * 65;
    float* Vs   = Ks + 64 * 65;
    float* Ps   = Vs + 64 * 65;
    float* m_sh = Ps + 64 * 65;
    float* l_sh = m_sh + 64;
    float* c_sh = l_sh + 64;

    const int tid = threadIdx.x;
    const int qt  = blockIdx.x;
    const int h   = blockIdx.y;
    const int b   = blockIdx.z;
    const int q0  = qt * 64;

    const size_t headOff = (size_t)h * DK_;
    const float* Qb = Q + ((size_t)b * S_ + q0) * D_ + headOff;
    const float* Kb = K + (size_t)b * S_ * D_ + headOff;
    const float* Vb = V + (size_t)b * S_ * D_ + headOff;

#pragma unroll
    for (int i = 0; i < 16; i++) {
        int lin = tid + i * 256;
        int r = lin >> 6, c = lin & 63;
        Qs[r * 65 + c] = Qb[(size_t)r * D_ + c];
    }
    if (tid < 64) { m_sh[tid] = -3.0e38f; l_sh[tid] = 0.0f; }

    const int ty = tid >> 4, tx = tid & 15;
    float oacc[4][4];
#pragma unroll
    for (int ii = 0; ii < 4; ii++)
#pragma unroll
        for (int jj = 0; jj < 4; jj++) oacc[ii][jj] = 0.0f;

    for (int jt = 0; jt < S_; jt += 64) {
        __syncthreads();
#pragma unroll
        for (int i = 0; i < 16; i++) {
            int lin = tid + i * 256;
            int r = lin >> 6, c = lin & 63;
            Ks[r * 65 + c] = Kb[(size_t)(jt + r) * D_ + c];
            Vs[r * 65 + c] = Vb[(size_t)(jt + r) * D_ + c];
        }
        __syncthreads();

        float sreg[4][4];
#pragma unroll
        for (int ii = 0; ii < 4; ii++)
#pragma unroll
            for (int jj = 0; jj < 4; jj++) sreg[ii][jj] = 0.0f;

#pragma unroll 8
        for (int d = 0; d < 64; d++) {
            float qv[4], kv[4];
#pragma unroll
            for (int ii = 0; ii < 4; ii++) qv[ii] = Qs[(ty * 4 + ii) * 65 + d];
#pragma unroll
            for (int jj = 0; jj < 4; jj++) kv[jj] = Ks[(tx * 4 + jj) * 65 + d];
#pragma unroll
            for (int ii = 0; ii < 4; ii++)
#pragma unroll
                for (int jj = 0; jj < 4; jj++)
                    sreg[ii][jj] += qv[ii] * kv[jj];
        }

#pragma unroll
        for (int ii = 0; ii < 4; ii++)
#pragma unroll
            for (int jj = 0; jj < 4; jj++)
                Ps[(ty * 4 + ii) * 65 + tx * 4 + jj] = sreg[ii][jj] * 0.125f;
        __syncthreads();

        if (tid < 64) {
            const int r = tid;
            float mold = m_sh[r];
            float mnew = mold;
#pragma unroll 8
            for (int j = 0; j < 64; j++) mnew = fmaxf(mnew, Ps[r * 65 + j]);
            float corr = __expf(mold - mnew);
            float ls = 0.0f;
#pragma unroll 8
            for (int j = 0; j < 64; j++) {
                float e = __expf(Ps[r * 65 + j] - mnew);
                Ps[r * 65 + j] = e;
                ls += e;
            }
            l_sh[r] = l_sh[r] * corr + ls;
            m_sh[r] = mnew;
            c_sh[r] = corr;
        }
        __syncthreads();

        float cr[4];
#pragma unroll
        for (int ii = 0; ii < 4; ii++) cr[ii] = c_sh[ty * 4 + ii];
#pragma unroll
        for (int ii = 0; ii < 4; ii++)
#pragma unroll
            for (int jj = 0; jj < 4; jj++) oacc[ii][jj] *= cr[ii];

#pragma unroll 8
        for (int j = 0; j < 64; j++) {
            float pv[4], vv[4];
#pragma unroll
            for (int ii = 0; ii < 4; ii++) pv[ii] = Ps[(ty * 4 + ii) * 65 + j];
#pragma unroll
            for (int jj = 0; jj < 4; jj++) vv[jj] = Vs[j * 65 + tx * 4 + jj];
#pragma unroll
            for (int ii = 0; ii < 4; ii++)
#pragma unroll
                for (int jj = 0; jj < 4; jj++)
                    oacc[ii][jj] += pv[ii] * vv[jj];
        }
    }

    float* Ob = O + ((size_t)b * S_ + q0) * D_ + headOff;
#pragma unroll
    for (int ii = 0; ii < 4; ii++) {
        float inv = 1.0f / l_sh[ty * 4 + ii];
#pragma unroll
        for (int jj = 0; jj < 4; jj++)
            Ob[(size_t)(ty * 4 + ii) * D_ + tx * 4 + jj] = oacc[ii][jj] * inv;
    }
}

// ---------------------------------------------------------------------------
// kernel_launch
// ---------------------------------------------------------------------------
extern "C" void kernel_launch(void* const* d_in, const int* in_sizes, int n_in,
                              void* d_out, int out_size)
{
    const float* q  = (const float*)d_in[0];
    const float* k  = (const float*)d_in[1];
    const float* v  = (const float*)d_in[2];
    const float* wq = (const float*)d_in[3];
    const float* bq = (const float*)d_in[4];
    const float* wk = (const float*)d_in[5];
    const float* bk = (const float*)d_in[6];
    const float* wv = (const float*)d_in[7];
    const float* bv = (const float*)d_in[8];
    const float* wo = (const float*)d_in[9];
    const float* bo = (const float*)d_in[10];
    float* out = (float*)d_out;

    float *gQ, *gK, *gV, *gO;
    __nv_bfloat16 *gAhi, *gAlo, *gWhi, *gWlo;
    cudaGetSymbolAddress((void**)&gQ, g_Q);
    cudaGetSymbolAddress((void**)&gK, g_K);
    cudaGetSymbolAddress((void**)&gV, g_V);
    cudaGetSymbolAddress((void**)&gO, g_O);
    cudaGetSymbolAddress((void**)&gAhi, g_Ahi);
    cudaGetSymbolAddress((void**)&gAlo, g_Alo);
    cudaGetSymbolAddress((void**)&gWhi, g_Whi);
    cudaGetSymbolAddress((void**)&gWlo, g_Wlo);

    cudaFuncSetAttribute(gemm_hmma,
                         cudaFuncAttributeMaxDynamicSharedMemorySize, GSMEM);

    const int n4 = M_ * D_ / 4;
    dim3 sgrid(n4 / 256), sblk(256);
    dim3 tgrid(D_ / 32, D_ / 32), tblk(32, 8);
    dim3 ggrid(D_ / 128, M_ / 128);   // (8, 64)

    // Q projection
    transpose_split_kernel<<<tgrid, tblk>>>(wq, gWhi, gWlo);
    split_kernel<<<sgrid, sblk>>>(q, gAhi, gAlo, n4);
    gemm_hmma<<<ggrid, 256, GSMEM>>>(gAhi, gAlo, gWhi, gWlo, bq, gQ);
    // K projection
    transpose_split_kernel<<<tgrid, tblk>>>(wk, gWhi, gWlo);
    split_kernel<<<sgrid, sblk>>>(k, gAhi, gAlo, n4);
    gemm_hmma<<<ggrid, 256, GSMEM>>>(gAhi, gAlo, gWhi, gWlo, bk, gK);
    // V projection
    transpose_split_kernel<<<tgrid, tblk>>>(wv, gWhi, gWlo);
    split_kernel<<<sgrid, sblk>>>(v, gAhi, gAlo, n4);
    gemm_hmma<<<ggrid, 256, GSMEM>>>(gAhi, gAlo, gWhi, gWlo, bv, gV);

    // attention
    size_t smem = (size_t)(4 * 64 * 65 + 3 * 64) * sizeof(float);
    cudaFuncSetAttribute(attn_kernel, cudaFuncAttributeMaxDynamicSharedMemorySize,
                         (int)smem);
    attn_kernel<<<dim3(S_ / 64, H_, B_), 256, smem>>>(gQ, gK, gV, gO);

    // output projection
    transpose_split_kernel<<<tgrid, tblk>>>(wo, gWhi, gWlo);
    split_kernel<<<sgrid, sblk>>>(gO, gAhi, gAlo, n4);
    gemm_hmma<<<ggrid, 256, GSMEM>>>(gAhi, gAlo, gWhi, gWlo, bo, out);
}

// round 5
// speedup vs baseline: 2.8177x; 2.1282x over previous
#include <cuda_runtime.h>
#include <cuda_bf16.h>
#include <cstdint>

// Problem constants
#define B_   4
#define S_   2048
#define D_   1024
#define H_   16
#define DK_  64
#define M_   (B_ * S_)   // 8192

// ---------------------------------------------------------------------------
// Scratch (device globals — no allocations allowed)
// ---------------------------------------------------------------------------
__device__ __nv_bfloat16 g_Ahi[(size_t)M_ * D_];   // activation split in; O split out
__device__ __nv_bfloat16 g_Alo[(size_t)M_ * D_];
__device__ __nv_bfloat16 g_Whi[(size_t)D_ * D_];   // transposed weight: [N, K]
__device__ __nv_bfloat16 g_Wlo[(size_t)D_ * D_];
__device__ __nv_bfloat16 g_Qhi[(size_t)M_ * D_];
__device__ __nv_bfloat16 g_Qlo[(size_t)M_ * D_];
__device__ __nv_bfloat16 g_Khi[(size_t)M_ * D_];
__device__ __nv_bfloat16 g_Klo[(size_t)M_ * D_];
__device__ __nv_bfloat16 g_Vhi[(size_t)M_ * D_];
__device__ __nv_bfloat16 g_Vlo[(size_t)M_ * D_];

// ---------------------------------------------------------------------------
// Helpers (base-target PTX only: ldmatrix / mma.sync / cp.async)
// ---------------------------------------------------------------------------
__device__ __forceinline__ uint32_t smem_to_u32(const void* p) {
    uint32_t a;
    asm("{ .reg .u64 t; cvta.to.shared.u64 t, %1; cvt.u32.u64 %0, t; }"
        : "=r"(a) : "l"(p));
    return a;
}
__device__ __forceinline__ void ldsm_x4(uint32_t* r, uint32_t addr) {
    asm volatile("ldmatrix.sync.aligned.m8n8.x4.shared.b16 {%0,%1,%2,%3}, [%4];"
        : "=r"(r[0]), "=r"(r[1]), "=r"(r[2]), "=r"(r[3]) : "r"(addr));
}
__device__ __forceinline__ void ldsm_x4_t(uint32_t* r, uint32_t addr) {
    asm volatile("ldmatrix.sync.aligned.m8n8.x4.trans.shared.b16 {%0,%1,%2,%3}, [%4];"
        : "=r"(r[0]), "=r"(r[1]), "=r"(r[2]), "=r"(r[3]) : "r"(addr));
}
__device__ __forceinline__ void mma_bf16(float* c, const uint32_t* a,
                                         uint32_t b0, uint32_t b1) {
    asm volatile(
        "mma.sync.aligned.m16n8k16.row.col.f32.bf16.bf16.f32 "
        "{%0,%1,%2,%3}, {%4,%5,%6,%7}, {%8,%9}, {%0,%1,%2,%3};"
        : "+f"(c[0]), "+f"(c[1]), "+f"(c[2]), "+f"(c[3])
        : "r"(a[0]), "r"(a[1]), "r"(a[2]), "r"(a[3]), "r"(b0), "r"(b1));
}
__device__ __forceinline__ void cp16(uint32_t dst, const void* src) {
    asm volatile("cp.async.cg.shared.global [%0], [%1], 16;\n" :: "r"(dst), "l"(src));
}
__device__ __forceinline__ void cp_commit() {
    asm volatile("cp.async.commit_group;\n" ::: "memory");
}
__device__ __forceinline__ uint32_t pk_bf16x2(float a, float b) {
    __nv_bfloat162 t = __float22bfloat162_rn(make_float2(a, b));
    return *reinterpret_cast<uint32_t*>(&t);
}
// pack pair into bf16 hi and residual lo words
__device__ __forceinline__ void pk_split2(float a, float b,
                                          uint32_t& hi, uint32_t& lo) {
    __nv_bfloat16 ha = __float2bfloat16(a), hb = __float2bfloat16(b);
    __nv_bfloat162 th = __halves2bfloat162(ha, hb);
    __nv_bfloat162 tl = __halves2bfloat162(
        __float2bfloat16(a - __bfloat162float(ha)),
        __float2bfloat16(b - __bfloat162float(hb)));
    hi = *reinterpret_cast<uint32_t*>(&th);
    lo = *reinterpret_cast<uint32_t*>(&tl);
}
// ldmatrix x4 address for 128B-row, 8-chunk XOR-swizzled tiles
__device__ __forceinline__ uint32_t ldsm_addr(uint32_t base, int row0, int ch0, int lane) {
    int row = row0 + (lane & 7) + ((lane >> 3) & 1) * 8;
    int ch  = ch0 + (lane >> 4);
    return base + (uint32_t)(row * 128) + (uint32_t)(((ch ^ (row & 7)) & 7) << 4);
}

// ---------------------------------------------------------------------------
// bf16 split kernels (inputs only; GEMM/attn epilogues split their own output)
// ---------------------------------------------------------------------------
__global__ void split_kernel(const float* __restrict__ x,
                             __nv_bfloat16* __restrict__ hi,
                             __nv_bfloat16* __restrict__ lo, int n4)
{
    int i = blockIdx.x * blockDim.x + threadIdx.x;
    if (i >= n4) return;
    float4 v = ((const float4*)x)[i];
    __nv_bfloat16 h0 = __float2bfloat16(v.x), h1 = __float2bfloat16(v.y);
    __nv_bfloat16 h2 = __float2bfloat16(v.z), h3 = __float2bfloat16(v.w);
    __nv_bfloat16 l0 = __float2bfloat16(v.x - __bfloat162float(h0));
    __nv_bfloat16 l1 = __float2bfloat16(v.y - __bfloat162float(h1));
    __nv_bfloat16 l2 = __float2bfloat16(v.z - __bfloat162float(h2));
    __nv_bfloat16 l3 = __float2bfloat16(v.w - __bfloat162float(h3));
    __nv_bfloat162* hp = (__nv_bfloat162*)(hi + (size_t)i * 4);
    __nv_bfloat162* lp = (__nv_bfloat162*)(lo + (size_t)i * 4);
    hp[0] = __halves2bfloat162(h0, h1); hp[1] = __halves2bfloat162(h2, h3);
    lp[0] = __halves2bfloat162(l0, l1); lp[1] = __halves2bfloat162(l2, l3);
}

__global__ void transpose_split_kernel(const float* __restrict__ w,
                                       __nv_bfloat16* __restrict__ hi,
                                       __nv_bfloat16* __restrict__ lo)
{
    __shared__ float t[32][33];
    int tx = threadIdx.x, ty = threadIdx.y;
    int bx = blockIdx.x * 32, by = blockIdx.y * 32;
#pragma unroll
    for (int i = 0; i < 4; i++)
        t[ty + i * 8][tx] = w[(size_t)(by + ty + i * 8) * D_ + bx + tx];
    __syncthreads();
#pragma unroll
    for (int i = 0; i < 4; i++) {
        float v = t[tx][ty + i * 8];
        __nv_bfloat16 h = __float2bfloat16(v);
        __nv_bfloat16 l = __float2bfloat16(v - __bfloat162float(h));
        size_t o = (size_t)(bx + ty + i * 8) * D_ + by + tx;
        hi[o] = h; lo[o] = l;
    }
}

// ---------------------------------------------------------------------------
// HMMA bf16-split GEMM (epilogue emits fp32 OR bf16 hi/lo)
// ---------------------------------------------------------------------------
#define BK_        32
#define STAGE_B    32768
#define AH_OFF     0
#define AL_OFF     8192
#define BH_OFF     16384
#define BL_OFF     24576
#define GSMEM      (2 * STAGE_B)
#define NSTAGES    (D_ / BK_)

__device__ __forceinline__ void load_stage(uint32_t smem_u, int buf,
    const __nv_bfloat16* __restrict__ Ah, const __nv_bfloat16* __restrict__ Al,
    const __nv_bfloat16* __restrict__ Bh, const __nv_bfloat16* __restrict__ Bl,
    int m0, int n0, int kt, int tid)
{
    const int row = tid >> 1;
    const int c0  = (tid & 1) * 2;
    const int swr = (row >> 1) & 3;
    const uint32_t sb = smem_u + (uint32_t)buf * STAGE_B;
    const uint32_t rowoff = (uint32_t)row * 64;
    const size_t ga = (size_t)(m0 + row) * D_ + kt;
    const size_t gb = (size_t)(n0 + row) * D_ + kt;
#pragma unroll
    for (int cc = 0; cc < 2; cc++) {
        int c = c0 + cc;
        uint32_t so = rowoff + (uint32_t)((c ^ swr) << 4);
        cp16(sb + AH_OFF + so, Ah + ga + c * 8);
        cp16(sb + AL_OFF + so, Al + ga + c * 8);
        cp16(sb + BH_OFF + so, Bh + gb + c * 8);
        cp16(sb + BL_OFF + so, Bl + gb + c * 8);
    }
}

__global__ __launch_bounds__(256, 1)
void gemm_hmma(const __nv_bfloat16* __restrict__ Ahi,
               const __nv_bfloat16* __restrict__ Alo,
               const __nv_bfloat16* __restrict__ Bhi,
               const __nv_bfloat16* __restrict__ Blo,
               const float* __restrict__ bias,
               float* __restrict__ Cf,
               __nv_bfloat16* __restrict__ Chi,
               __nv_bfloat16* __restrict__ Clo)
{
    extern __shared__ char smem[];
    const uint32_t smem_u = smem_to_u32(smem);
    const int tid = threadIdx.x;
    const int m0 = blockIdx.y * 128, n0 = blockIdx.x * 128;

    const int lane  = tid & 31;
    const int warpM = (tid >> 5) & 1;
    const int warpN = tid >> 6;
    const int qq = lane >> 3, rr = lane & 7;
    const int rbase = rr + (qq & 1) * 8;
    const int csel  = qq >> 1;

    int arow[4], brow[2];
#pragma unroll
    for (int i = 0; i < 4; i++) arow[i] = warpM * 64 + i * 16 + rbase;
#pragma unroll
    for (int j = 0; j < 2; j++) brow[j] = warpN * 32 + j * 16 + rbase;

    float acc[4][4][4];
#pragma unroll
    for (int i = 0; i < 4; i++)
#pragma unroll
        for (int j = 0; j < 4; j++)
#pragma unroll
            for (int r = 0; r < 4; r++) acc[i][j][r] = 0.0f;

    load_stage(smem_u, 0, Ahi, Alo, Bhi, Blo, m0, n0, 0, tid);
    cp_commit();
    load_stage(smem_u, 1, Ahi, Alo, Bhi, Blo, m0, n0, BK_, tid);
    cp_commit();

    for (int c = 0; c < NSTAGES; c++) {
        if (c < NSTAGES - 1)
            asm volatile("cp.async.wait_group 1;\n" ::: "memory");
        else
            asm volatile("cp.async.wait_group 0;\n" ::: "memory");
        __syncthreads();

        const uint32_t sb = smem_u + (uint32_t)(c & 1) * STAGE_B;
#pragma unroll
        for (int ks = 0; ks < 2; ks++) {
            uint32_t ah[4][4], al[4][4], bh[2][4], bl[2][4];
            const int kc = ks * 2 + csel;
#pragma unroll
            for (int i = 0; i < 4; i++) {
                int r = arow[i];
                uint32_t ad = sb + (uint32_t)(r * 64) +
                              (uint32_t)((kc ^ ((r >> 1) & 3)) << 4);
                ldsm_x4(ah[i], ad + AH_OFF);
                ldsm_x4(al[i], ad + AL_OFF);
            }
#pragma unroll
            for (int j = 0; j < 2; j++) {
                int r = brow[j];
                uint32_t bd = sb + (uint32_t)(r * 64) +
                              (uint32_t)((kc ^ ((r >> 1) & 3)) << 4);
                ldsm_x4(bh[j], bd + BH_OFF);
                ldsm_x4(bl[j], bd + BL_OFF);
            }
#pragma unroll
            for (int i = 0; i < 4; i++)
#pragma unroll
                for (int j = 0; j < 4; j++) {
                    const int j2 = j >> 1, p = j & 1;
                    mma_bf16(acc[i][j], ah[i], bh[j2][p], bh[j2][p + 2]);
                    mma_bf16(acc[i][j], ah[i], bl[j2][p], bl[j2][p + 2]);
                    mma_bf16(acc[i][j], al[i], bh[j2][p], bh[j2][p + 2]);
                }
        }
        __syncthreads();
        if (c + 2 < NSTAGES) {
            load_stage(smem_u, c & 1, Ahi, Alo, Bhi, Blo, m0, n0,
                       (c + 2) * BK_, tid);
            cp_commit();
        }
    }

    const int crow = lane >> 2, ccol = (lane & 3) * 2;
#pragma unroll
    for (int i = 0; i < 4; i++) {
        const int gr = m0 + warpM * 64 + i * 16 + crow;
#pragma unroll
        for (int j = 0; j < 4; j++) {
            const int gc = n0 + warpN * 32 + j * 8 + ccol;
            const float b0 = __ldg(bias + gc), b1 = __ldg(bias + gc + 1);
            float v0 = acc[i][j][0] + b0, v1 = acc[i][j][1] + b1;
            float v2 = acc[i][j][2] + b0, v3 = acc[i][j][3] + b1;
            if (Cf) {
                *(float2*)(Cf + (size_t)gr * D_ + gc)       = make_float2(v0, v1);
                *(float2*)(Cf + (size_t)(gr + 8) * D_ + gc) = make_float2(v2, v3);
            } else {
                uint32_t h01, l01, h23, l23;
                pk_split2(v0, v1, h01, l01);
                pk_split2(v2, v3, h23, l23);
                *(uint32_t*)(Chi + (size_t)gr * D_ + gc)       = h01;
                *(uint32_t*)(Chi + (size_t)(gr + 8) * D_ + gc) = h23;
                *(uint32_t*)(Clo + (size_t)gr * D_ + gc)       = l01;
                *(uint32_t*)(Clo + (size_t)(gr + 8) * D_ + gc) = l23;
            }
        }
    }
}

// ---------------------------------------------------------------------------
// HMMA flash attention.
// CTA: 128 q-rows x one (b,h). 8 warps x 16 q-rows. kv tile 64, double buffer.
// QK^T: 3-term bf16 split. Softmax in registers (quad shfl).
// PV: (Phi+Plo) x (Vhi+Vlo), dropped Plo*Vlo cross term -> 3-term split.
// Output written directly as bf16 hi/lo splits.
// ---------------------------------------------------------------------------
#define ATT_SMEM   98304
#define NKV        (S_ / 64)   // 32

__device__ __forceinline__ void att_load_kv(uint32_t stg_base,
    const __nv_bfloat16* __restrict__ Khi, const __nv_bfloat16* __restrict__ Klo,
    const __nv_bfloat16* __restrict__ Vhi, const __nv_bfloat16* __restrict__ Vlo,
    size_t rowbase, int jt, int col0, int tid)
{
#pragma unroll
    for (int i = 0; i < 2; i++) {
        int c = tid + i * 256;             // 0..511
        int r = c >> 3, ch = c & 7;
        uint32_t so = (uint32_t)(r * 128 + (((ch ^ (r & 7)) & 7) << 4));
        const size_t g = (rowbase + jt + r) * D_ + col0 + ch * 8;
        cp16(stg_base + 0     + so, Khi + g);
        cp16(stg_base + 8192  + so, Klo + g);
        cp16(stg_base + 16384 + so, Vhi + g);
        cp16(stg_base + 24576 + so, Vlo + g);
    }
}

__global__ __launch_bounds__(256, 1)
void attn_hmma(const __nv_bfloat16* __restrict__ Qhi, const __nv_bfloat16* __restrict__ Qlo,
               const __nv_bfloat16* __restrict__ Khi, const __nv_bfloat16* __restrict__ Klo,
               const __nv_bfloat16* __restrict__ Vhi, const __nv_bfloat16* __restrict__ Vlo,
               __nv_bfloat16* __restrict__ Ohi, __nv_bfloat16* __restrict__ Olo)
{
    extern __shared__ char smem[];
    const uint32_t su = smem_to_u32(smem);
    const int tid = threadIdx.x, lane = tid & 31, warp = tid >> 5;
    const int q0 = blockIdx.x * 128;
    const int h  = blockIdx.y, b = blockIdx.z;
    const size_t rowbase = (size_t)b * S_;
    const int col0 = h * DK_;

    const uint32_t QHI = su, QLO = su + 16384;
    const uint32_t STG = su + 32768;

#pragma unroll
    for (int i = 0; i < 4; i++) {
        int c = tid + i * 256;             // 0..1023
        int r = c >> 3, ch = c & 7;
        uint32_t so = (uint32_t)(r * 128 + (((ch ^ (r & 7)) & 7) << 4));
        const size_t g = (rowbase + q0 + r) * D_ + col0 + ch * 8;
        cp16(QHI + so, Qhi + g);
        cp16(QLO + so, Qlo + g);
    }
    cp_commit();
    att_load_kv(STG, Khi, Klo, Vhi, Vlo, rowbase, 0, col0, tid);
    cp_commit();
    att_load_kv(STG + STAGE_B, Khi, Klo, Vhi, Vlo, rowbase, 64, col0, tid);
    cp_commit();

    asm volatile("cp.async.wait_group 2;\n" ::: "memory");
    __syncthreads();

    uint32_t qh[4][4], ql[4][4];
#pragma unroll
    for (int kc = 0; kc < 4; kc++) {
        ldsm_x4(qh[kc], ldsm_addr(QHI, warp * 16, kc * 2, lane));
        ldsm_x4(ql[kc], ldsm_addr(QLO, warp * 16, kc * 2, lane));
    }

    float oacc[8][4];
#pragma unroll
    for (int j = 0; j < 8; j++)
#pragma unroll
        for (int i = 0; i < 4; i++) oacc[j][i] = 0.0f;
    float m0 = -3.0e38f, m1 = -3.0e38f, l0 = 0.0f, l1 = 0.0f;

    for (int c = 0; c < NKV; c++) {
        if (c < NKV - 1)
            asm volatile("cp.async.wait_group 1;\n" ::: "memory");
        else
            asm volatile("cp.async.wait_group 0;\n" ::: "memory");
        __syncthreads();

        const uint32_t KB = STG + (uint32_t)(c & 1) * STAGE_B;

        // ---- S = Q @ K^T  (3-term split), S tile [16 q, 64 kv] per warp
        float sacc[8][4];
#pragma unroll
        for (int j = 0; j < 8; j++)
#pragma unroll
            for (int i = 0; i < 4; i++) sacc[j][i] = 0.0f;

#pragma unroll
        for (int kc = 0; kc < 4; kc++) {
            uint32_t kh[4][4], kl[4][4];
#pragma unroll
            for (int ng = 0; ng < 4; ng++) {
                ldsm_x4(kh[ng], ldsm_addr(KB + 0,    ng * 16, kc * 2, lane));
                ldsm_x4(kl[ng], ldsm_addr(KB + 8192, ng * 16, kc * 2, lane));
            }
#pragma unroll
            for (int j = 0; j < 8; j++) {
                const int g = j >> 1, p = j & 1;
                mma_bf16(sacc[j], qh[kc], kh[g][p], kh[g][p + 2]);
                mma_bf16(sacc[j], qh[kc], kl[g][p], kl[g][p + 2]);
                mma_bf16(sacc[j], ql[kc], kh[g][p], kh[g][p + 2]);
            }
        }

        // ---- online softmax in registers (rows lane>>2 and +8)
#pragma unroll
        for (int j = 0; j < 8; j++)
#pragma unroll
            for (int i = 0; i < 4; i++) sacc[j][i] *= 0.125f;

        float mx0 = -3.0e38f, mx1 = -3.0e38f;
#pragma unroll
        for (int j = 0; j < 8; j++) {
            mx0 = fmaxf(mx0, fmaxf(sacc[j][0], sacc[j][1]));
            mx1 = fmaxf(mx1, fmaxf(sacc[j][2], sacc[j][3]));
        }
        mx0 = fmaxf(mx0, __shfl_xor_sync(0xffffffffu, mx0, 1));
        mx0 = fmaxf(mx0, __shfl_xor_sync(0xffffffffu, mx0, 2));
        mx1 = fmaxf(mx1, __shfl_xor_sync(0xffffffffu, mx1, 1));
        mx1 = fmaxf(mx1, __shfl_xor_sync(0xffffffffu, mx1, 2));

        float mn0 = fmaxf(m0, mx0), mn1 = fmaxf(m1, mx1);
        float corr0 = __expf(m0 - mn0), corr1 = __expf(m1 - mn1);
        m0 = mn0; m1 = mn1;

        float s0 = 0.0f, s1 = 0.0f;
#pragma unroll
        for (int j = 0; j < 8; j++) {
            sacc[j][0] = __expf(sacc[j][0] - mn0);
            sacc[j][1] = __expf(sacc[j][1] - mn0);
            sacc[j][2] = __expf(sacc[j][2] - mn1);
            sacc[j][3] = __expf(sacc[j][3] - mn1);
            s0 += sacc[j][0] + sacc[j][1];
            s1 += sacc[j][2] + sacc[j][3];
        }
        s0 += __shfl_xor_sync(0xffffffffu, s0, 1);
        s0 += __shfl_xor_sync(0xffffffffu, s0, 2);
        s1 += __shfl_xor_sync(0xffffffffu, s1, 1);
        s1 += __shfl_xor_sync(0xffffffffu, s1, 2);
        l0 = l0 * corr0 + s0;
        l1 = l1 * corr1 + s1;

#pragma unroll
        for (int j = 0; j < 8; j++) {
            oacc[j][0] *= corr0; oacc[j][1] *= corr0;
            oacc[j][2] *= corr1; oacc[j][3] *= corr1;
        }

        // ---- O += (Phi+Plo) @ (Vhi+Vlo) minus Plo*Vlo cross term
#pragma unroll
        for (int kc = 0; kc < 4; kc++) {
            uint32_t ph[4], pl[4];
            pk_split2(sacc[2 * kc][0],     sacc[2 * kc][1],     ph[0], pl[0]);
            pk_split2(sacc[2 * kc][2],     sacc[2 * kc][3],     ph[1], pl[1]);
            pk_split2(sacc[2 * kc + 1][0], sacc[2 * kc + 1][1], ph[2], pl[2]);
            pk_split2(sacc[2 * kc + 1][2], sacc[2 * kc + 1][3], ph[3], pl[3]);
#pragma unroll
            for (int dg = 0; dg < 4; dg++) {
                uint32_t vh[4], vl[4];
                ldsm_x4_t(vh, ldsm_addr(KB + 16384, kc * 16, dg * 2, lane));
                ldsm_x4_t(vl, ldsm_addr(KB + 24576, kc * 16, dg * 2, lane));
                mma_bf16(oacc[2 * dg],     ph, vh[0], vh[1]);
                mma_bf16(oacc[2 * dg + 1], ph, vh[2], vh[3]);
                mma_bf16(oacc[2 * dg],     ph, vl[0], vl[1]);
                mma_bf16(oacc[2 * dg + 1], ph, vl[2], vl[3]);
                mma_bf16(oacc[2 * dg],     pl, vh[0], vh[1]);
                mma_bf16(oacc[2 * dg + 1], pl, vh[2], vh[3]);
            }
        }

        __syncthreads();
        if (c + 2 < NKV) {
            att_load_kv(STG + (uint32_t)(c & 1) * STAGE_B,
                        Khi, Klo, Vhi, Vlo, rowbase, (c + 2) * 64, col0, tid);
            cp_commit();
        }
    }

    // ---- epilogue: normalize, split to bf16 hi/lo, store
    const float inv0 = 1.0f / l0, inv1 = 1.0f / l1;
    const int r0 = warp * 16 + (lane >> 2);
    const int c0 = (lane & 3) * 2;
#pragma unroll
    for (int j = 0; j < 8; j++) {
        const int dcol = col0 + j * 8 + c0;
        const size_t o0 = (rowbase + q0 + r0) * D_ + dcol;
        const size_t o1 = (rowbase + q0 + r0 + 8) * D_ + dcol;
        uint32_t h01, l01, h23, l23;
        pk_split2(oacc[j][0] * inv0, oacc[j][1] * inv0, h01, l01);
        pk_split2(oacc[j][2] * inv1, oacc[j][3] * inv1, h23, l23);
        *(uint32_t*)(Ohi + o0) = h01;
        *(uint32_t*)(Ohi + o1) = h23;
        *(uint32_t*)(Olo + o0) = l01;
        *(uint32_t*)(Olo + o1) = l23;
    }
}

// ---------------------------------------------------------------------------
// kernel_launch
// ---------------------------------------------------------------------------
extern "C" void kernel_launch(void* const* d_in, const int* in_sizes, int n_in,
                              void* d_out, int out_size)
{
    const float* q  = (const float*)d_in[0];
    const float* k  = (const float*)d_in[1];
    const float* v  = (const float*)d_in[2];
    const float* wq = (const float*)d_in[3];
    const float* bq = (const float*)d_in[4];
    const float* wk = (const float*)d_in[5];
    const float* bk = (const float*)d_in[6];
    const float* wv = (const float*)d_in[7];
    const float* bv = (const float*)d_in[8];
    const float* wo = (const float*)d_in[9];
    const float* bo = (const float*)d_in[10];
    float* out = (float*)d_out;

    __nv_bfloat16 *gAhi, *gAlo, *gWhi, *gWlo;
    __nv_bfloat16 *gQhi, *gQlo, *gKhi, *gKlo, *gVhi, *gVlo;
    cudaGetSymbolAddress((void**)&gAhi, g_Ahi);
    cudaGetSymbolAddress((void**)&gAlo, g_Alo);
    cudaGetSymbolAddress((void**)&gWhi, g_Whi);
    cudaGetSymbolAddress((void**)&gWlo, g_Wlo);
    cudaGetSymbolAddress((void**)&gQhi, g_Qhi);
    cudaGetSymbolAddress((void**)&gQlo, g_Qlo);
    cudaGetSymbolAddress((void**)&gKhi, g_Khi);
    cudaGetSymbolAddress((void**)&gKlo, g_Klo);
    cudaGetSymbolAddress((void**)&gVhi, g_Vhi);
    cudaGetSymbolAddress((void**)&gVlo, g_Vlo);

    cudaFuncSetAttribute(gemm_hmma,
                         cudaFuncAttributeMaxDynamicSharedMemorySize, GSMEM);
    cudaFuncSetAttribute(attn_hmma,
                         cudaFuncAttributeMaxDynamicSharedMemorySize, ATT_SMEM);

    const int n4 = M_ * D_ / 4;
    dim3 sgrid(n4 / 256), sblk(256);
    dim3 tgrid(D_ / 32, D_ / 32), tblk(32, 8);
    dim3 ggrid(D_ / 128, M_ / 128);

    // Q projection -> bf16 hi/lo
    transpose_split_kernel<<<tgrid, tblk>>>(wq, gWhi, gWlo);
    split_kernel<<<sgrid, sblk>>>(q, gAhi, gAlo, n4);
    gemm_hmma<<<ggrid, 256, GSMEM>>>(gAhi, gAlo, gWhi, gWlo, bq,
                                     nullptr, gQhi, gQlo);
    // K projection
    transpose_split_kernel<<<tgrid, tblk>>>(wk, gWhi, gWlo);
    split_kernel<<<sgrid, sblk>>>(k, gAhi, gAlo, n4);
    gemm_hmma<<<ggrid, 256, GSMEM>>>(gAhi, gAlo, gWhi, gWlo, bk,
                                     nullptr, gKhi, gKlo);
    // V projection
    transpose_split_kernel<<<tgrid, tblk>>>(wv, gWhi, gWlo);
    split_kernel<<<sgrid, sblk>>>(v, gAhi, gAlo, n4);
    gemm_hmma<<<ggrid, 256, GSMEM>>>(gAhi, gAlo, gWhi, gWlo, bv,
                                     nullptr, gVhi, gVlo);

    // attention -> O split directly into gAhi/gAlo
    attn_hmma<<<dim3(S_ / 128, H_, B_), 256, ATT_SMEM>>>(
        gQhi, gQlo, gKhi, gKlo, gVhi, gVlo, gAhi, gAlo);

    // output projection -> fp32 out
    transpose_split_kernel<<<tgrid, tblk>>>(wo, gWhi, gWlo);
    gemm_hmma<<<ggrid, 256, GSMEM>>>(gAhi, gAlo, gWhi, gWlo, bo,
                                     out, nullptr, nullptr);
}

// round 6
// speedup vs baseline: 3.1029x; 1.1012x over previous
#include <cuda_runtime.h>
#include <cuda_bf16.h>
#include <cstdint>

// Problem constants
#define B_   4
#define S_   2048
#define D_   1024
#define H_   16
#define DK_  64
#define M_   (B_ * S_)   // 8192

// ---------------------------------------------------------------------------
// Scratch (device globals — no allocations allowed)
// ---------------------------------------------------------------------------
__device__ __nv_bfloat16 g_Xqhi[(size_t)M_ * D_];  // input splits; Xq reused for O
__device__ __nv_bfloat16 g_Xqlo[(size_t)M_ * D_];
__device__ __nv_bfloat16 g_Xkhi[(size_t)M_ * D_];
__device__ __nv_bfloat16 g_Xklo[(size_t)M_ * D_];
__device__ __nv_bfloat16 g_Xvhi[(size_t)M_ * D_];
__device__ __nv_bfloat16 g_Xvlo[(size_t)M_ * D_];
__device__ __nv_bfloat16 g_WQhi[(size_t)D_ * D_];  // transposed weights [N,K]
__device__ __nv_bfloat16 g_WQlo[(size_t)D_ * D_];
__device__ __nv_bfloat16 g_WKhi[(size_t)D_ * D_];
__device__ __nv_bfloat16 g_WKlo[(size_t)D_ * D_];
__device__ __nv_bfloat16 g_WVhi[(size_t)D_ * D_];
__device__ __nv_bfloat16 g_WVlo[(size_t)D_ * D_];
__device__ __nv_bfloat16 g_WOhi[(size_t)D_ * D_];
__device__ __nv_bfloat16 g_WOlo[(size_t)D_ * D_];
__device__ __nv_bfloat16 g_Qhi[(size_t)M_ * D_];   // projection outputs
__device__ __nv_bfloat16 g_Qlo[(size_t)M_ * D_];
__device__ __nv_bfloat16 g_Khi[(size_t)M_ * D_];
__device__ __nv_bfloat16 g_Klo[(size_t)M_ * D_];
__device__ __nv_bfloat16 g_Vhi[(size_t)M_ * D_];
__device__ __nv_bfloat16 g_Vlo[(size_t)M_ * D_];

// ---------------------------------------------------------------------------
// Helpers (base-target PTX only: ldmatrix / mma.sync / cp.async)
// ---------------------------------------------------------------------------
__device__ __forceinline__ uint32_t smem_to_u32(const void* p) {
    uint32_t a;
    asm("{ .reg .u64 t; cvta.to.shared.u64 t, %1; cvt.u32.u64 %0, t; }"
        : "=r"(a) : "l"(p));
    return a;
}
__device__ __forceinline__ void ldsm_x4(uint32_t* r, uint32_t addr) {
    asm volatile("ldmatrix.sync.aligned.m8n8.x4.shared.b16 {%0,%1,%2,%3}, [%4];"
        : "=r"(r[0]), "=r"(r[1]), "=r"(r[2]), "=r"(r[3]) : "r"(addr));
}
__device__ __forceinline__ void ldsm_x4_t(uint32_t* r, uint32_t addr) {
    asm volatile("ldmatrix.sync.aligned.m8n8.x4.trans.shared.b16 {%0,%1,%2,%3}, [%4];"
        : "=r"(r[0]), "=r"(r[1]), "=r"(r[2]), "=r"(r[3]) : "r"(addr));
}
__device__ __forceinline__ void mma_bf16(float* c, const uint32_t* a,
                                         uint32_t b0, uint32_t b1) {
    asm volatile(
        "mma.sync.aligned.m16n8k16.row.col.f32.bf16.bf16.f32 "
        "{%0,%1,%2,%3}, {%4,%5,%6,%7}, {%8,%9}, {%0,%1,%2,%3};"
        : "+f"(c[0]), "+f"(c[1]), "+f"(c[2]), "+f"(c[3])
        : "r"(a[0]), "r"(a[1]), "r"(a[2]), "r"(a[3]), "r"(b0), "r"(b1));
}
__device__ __forceinline__ void cp16(uint32_t dst, const void* src) {
    asm volatile("cp.async.cg.shared.global [%0], [%1], 16;\n" :: "r"(dst), "l"(src));
}
__device__ __forceinline__ void cp_commit() {
    asm volatile("cp.async.commit_group;\n" ::: "memory");
}
__device__ __forceinline__ void pk_split2(float a, float b,
                                          uint32_t& hi, uint32_t& lo) {
    __nv_bfloat16 ha = __float2bfloat16(a), hb = __float2bfloat16(b);
    __nv_bfloat162 th = __halves2bfloat162(ha, hb);
    __nv_bfloat162 tl = __halves2bfloat162(
        __float2bfloat16(a - __bfloat162float(ha)),
        __float2bfloat16(b - __bfloat162float(hb)));
    hi = *reinterpret_cast<uint32_t*>(&th);
    lo = *reinterpret_cast<uint32_t*>(&tl);
}
// ldmatrix x4 address for 128B-row, 8-chunk XOR-swizzled tiles
__device__ __forceinline__ uint32_t ldsm_addr(uint32_t base, int row0, int ch0, int lane) {
    int row = row0 + (lane & 7) + ((lane >> 3) & 1) * 8;
    int ch  = ch0 + (lane >> 4);
    return base + (uint32_t)(row * 128) + (uint32_t)(((ch ^ (row & 7)) & 7) << 4);
}

// ---------------------------------------------------------------------------
// Fused input-split (3 tensors) and weight transpose-split (4 weights)
// ---------------------------------------------------------------------------
struct SP3 { const float* x[3]; __nv_bfloat16* hi[3]; __nv_bfloat16* lo[3]; };
struct TS4 { const float* w[4]; __nv_bfloat16* hi[4]; __nv_bfloat16* lo[4]; };

__global__ void split3_kernel(SP3 p, int n4)
{
    int i = blockIdx.x * blockDim.x + threadIdx.x;
    if (i >= n4) return;
    const int z = blockIdx.z;
    float4 v = ((const float4*)p.x[z])[i];
    __nv_bfloat16 h0 = __float2bfloat16(v.x), h1 = __float2bfloat16(v.y);
    __nv_bfloat16 h2 = __float2bfloat16(v.z), h3 = __float2bfloat16(v.w);
    __nv_bfloat16 l0 = __float2bfloat16(v.x - __bfloat162float(h0));
    __nv_bfloat16 l1 = __float2bfloat16(v.y - __bfloat162float(h1));
    __nv_bfloat16 l2 = __float2bfloat16(v.z - __bfloat162float(h2));
    __nv_bfloat16 l3 = __float2bfloat16(v.w - __bfloat162float(h3));
    __nv_bfloat162* hp = (__nv_bfloat162*)(p.hi[z] + (size_t)i * 4);
    __nv_bfloat162* lp = (__nv_bfloat162*)(p.lo[z] + (size_t)i * 4);
    hp[0] = __halves2bfloat162(h0, h1); hp[1] = __halves2bfloat162(h2, h3);
    lp[0] = __halves2bfloat162(l0, l1); lp[1] = __halves2bfloat162(l2, l3);
}

__global__ void transpose_split4_kernel(TS4 p)
{
    __shared__ float t[32][33];
    const int z = blockIdx.z;
    const float* w = p.w[z];
    int tx = threadIdx.x, ty = threadIdx.y;
    int bx = blockIdx.x * 32, by = blockIdx.y * 32;
#pragma unroll
    for (int i = 0; i < 4; i++)
        t[ty + i * 8][tx] = w[(size_t)(by + ty + i * 8) * D_ + bx + tx];
    __syncthreads();
#pragma unroll
    for (int i = 0; i < 4; i++) {
        float v = t[tx][ty + i * 8];
        __nv_bfloat16 h = __float2bfloat16(v);
        __nv_bfloat16 l = __float2bfloat16(v - __bfloat162float(h));
        size_t o = (size_t)(bx + ty + i * 8) * D_ + by + tx;
        p.hi[z][o] = h; p.lo[z][o] = l;
    }
}

// ---------------------------------------------------------------------------
// HMMA bf16-split GEMM, BK=64, batched over blockIdx.z.
// 128x128 tile, 8 warps (2x4), 128B-row XOR-swizzled smem, double buffer.
// ---------------------------------------------------------------------------
#define BK_        64
#define G_TILE     16384                  // 128 rows x 128 bytes
#define G_AH       0
#define G_AL       16384
#define G_BH       32768
#define G_BL       49152
#define G_STAGE    65536
#define GSMEM      (2 * G_STAGE)          // 131072
#define NSTAGES    (D_ / BK_)             // 16

struct GArgs {
    const __nv_bfloat16 *Ah, *Al, *Bh, *Bl;
    const float* bias;
    float* Cf;
    __nv_bfloat16 *Chi, *Clo;
};
struct GBatch { GArgs g[3]; };

__device__ __forceinline__ void g_load_stage(uint32_t sb, const GArgs& a,
                                             int m0, int n0, int kt, int tid)
{
#pragma unroll
    for (int i = 0; i < 4; i++) {
        int c = tid + i * 256;              // 0..1023
        int r = c >> 3, ch = c & 7;
        uint32_t so = (uint32_t)(r * 128 + (((ch ^ (r & 7)) & 7) << 4));
        const size_t ga = (size_t)(m0 + r) * D_ + kt + ch * 8;
        const size_t gb = (size_t)(n0 + r) * D_ + kt + ch * 8;
        cp16(sb + G_AH + so, a.Ah + ga);
        cp16(sb + G_AL + so, a.Al + ga);
        cp16(sb + G_BH + so, a.Bh + gb);
        cp16(sb + G_BL + so, a.Bl + gb);
    }
}

__global__ __launch_bounds__(256, 1)
void gemm_hmma(GBatch batch)
{
    extern __shared__ char smem[];
    const uint32_t su = smem_to_u32(smem);
    const GArgs a = batch.g[blockIdx.z];
    const int tid = threadIdx.x, lane = tid & 31;
    const int m0 = blockIdx.y * 128, n0 = blockIdx.x * 128;
    const int warpM = (tid >> 5) & 1;     // 64 rows each
    const int warpN = tid >> 6;           // 32 cols each

    float acc[4][4][4];
#pragma unroll
    for (int i = 0; i < 4; i++)
#pragma unroll
        for (int j = 0; j < 4; j++)
#pragma unroll
            for (int r = 0; r < 4; r++) acc[i][j][r] = 0.0f;

    g_load_stage(su, a, m0, n0, 0, tid);
    cp_commit();
    g_load_stage(su + G_STAGE, a, m0, n0, BK_, tid);
    cp_commit();

    for (int c = 0; c < NSTAGES; c++) {
        if (c < NSTAGES - 1)
            asm volatile("cp.async.wait_group 1;\n" ::: "memory");
        else
            asm volatile("cp.async.wait_group 0;\n" ::: "memory");
        __syncthreads();

        const uint32_t sb = su + (uint32_t)(c & 1) * G_STAGE;
#pragma unroll
        for (int kc = 0; kc < 4; kc++) {
            uint32_t ah[4][4], al[4][4], bh[2][4], bl[2][4];
#pragma unroll
            for (int i = 0; i < 4; i++) {
                ldsm_x4(ah[i], ldsm_addr(sb + G_AH, warpM * 64 + i * 16, kc * 2, lane));
                ldsm_x4(al[i], ldsm_addr(sb + G_AL, warpM * 64 + i * 16, kc * 2, lane));
            }
#pragma unroll
            for (int j = 0; j < 2; j++) {
                ldsm_x4(bh[j], ldsm_addr(sb + G_BH, warpN * 32 + j * 16, kc * 2, lane));
                ldsm_x4(bl[j], ldsm_addr(sb + G_BL, warpN * 32 + j * 16, kc * 2, lane));
            }
#pragma unroll
            for (int i = 0; i < 4; i++)
#pragma unroll
                for (int j = 0; j < 4; j++) {
                    const int g = j >> 1, p = j & 1;
                    mma_bf16(acc[i][j], ah[i], bh[g][p], bh[g][p + 2]);
                    mma_bf16(acc[i][j], ah[i], bl[g][p], bl[g][p + 2]);
                    mma_bf16(acc[i][j], al[i], bh[g][p], bh[g][p + 2]);
                }
        }
        __syncthreads();
        if (c + 2 < NSTAGES) {
            g_load_stage(su + (uint32_t)(c & 1) * G_STAGE, a, m0, n0,
                         (c + 2) * BK_, tid);
            cp_commit();
        }
    }

    const int crow = lane >> 2, ccol = (lane & 3) * 2;
#pragma unroll
    for (int i = 0; i < 4; i++) {
        const int gr = m0 + warpM * 64 + i * 16 + crow;
#pragma unroll
        for (int j = 0; j < 4; j++) {
            const int gc = n0 + warpN * 32 + j * 8 + ccol;
            const float b0 = __ldg(a.bias + gc), b1 = __ldg(a.bias + gc + 1);
            float v0 = acc[i][j][0] + b0, v1 = acc[i][j][1] + b1;
            float v2 = acc[i][j][2] + b0, v3 = acc[i][j][3] + b1;
            if (a.Cf) {
                *(float2*)(a.Cf + (size_t)gr * D_ + gc)       = make_float2(v0, v1);
                *(float2*)(a.Cf + (size_t)(gr + 8) * D_ + gc) = make_float2(v2, v3);
            } else {
                uint32_t h01, l01, h23, l23;
                pk_split2(v0, v1, h01, l01);
                pk_split2(v2, v3, h23, l23);
                *(uint32_t*)(a.Chi + (size_t)gr * D_ + gc)       = h01;
                *(uint32_t*)(a.Chi + (size_t)(gr + 8) * D_ + gc) = h23;
                *(uint32_t*)(a.Clo + (size_t)gr * D_ + gc)       = l01;
                *(uint32_t*)(a.Clo + (size_t)(gr + 8) * D_ + gc) = l23;
            }
        }
    }
}

// ---------------------------------------------------------------------------
// HMMA flash attention. CTA: 64 q-rows, 4 warps, 2 CTAs/SM for softmax/MMA
// overlap. kv tile 64, double buffer. QK^T and PV both 3-term bf16 splits.
// smem: Q 16KB + 2 stages x 32KB = 80KB.
// ---------------------------------------------------------------------------
#define ATT_STAGE  32768
#define ATT_SMEM   (16384 + 2 * ATT_STAGE)   // 81920
#define NKV        (S_ / 64)                  // 32

__device__ __forceinline__ void att_load_kv(uint32_t stg_base,
    const __nv_bfloat16* __restrict__ Khi, const __nv_bfloat16* __restrict__ Klo,
    const __nv_bfloat16* __restrict__ Vhi, const __nv_bfloat16* __restrict__ Vlo,
    size_t rowbase, int jt, int col0, int tid)
{
#pragma unroll
    for (int i = 0; i < 4; i++) {
        int c = tid + i * 128;             // 0..511
        int r = c >> 3, ch = c & 7;
        uint32_t so = (uint32_t)(r * 128 + (((ch ^ (r & 7)) & 7) << 4));
        const size_t g = (rowbase + jt + r) * D_ + col0 + ch * 8;
        cp16(stg_base + 0     + so, Khi + g);
        cp16(stg_base + 8192  + so, Klo + g);
        cp16(stg_base + 16384 + so, Vhi + g);
        cp16(stg_base + 24576 + so, Vlo + g);
    }
}

__global__ __launch_bounds__(128, 2)
void attn_hmma(const __nv_bfloat16* __restrict__ Qhi, const __nv_bfloat16* __restrict__ Qlo,
               const __nv_bfloat16* __restrict__ Khi, const __nv_bfloat16* __restrict__ Klo,
               const __nv_bfloat16* __restrict__ Vhi, const __nv_bfloat16* __restrict__ Vlo,
               __nv_bfloat16* __restrict__ Ohi, __nv_bfloat16* __restrict__ Olo)
{
    extern __shared__ char smem[];
    const uint32_t su = smem_to_u32(smem);
    const int tid = threadIdx.x, lane = tid & 31, warp = tid >> 5;
    const int q0 = blockIdx.x * 64;
    const int h  = blockIdx.y, b = blockIdx.z;
    const size_t rowbase = (size_t)b * S_;
    const int col0 = h * DK_;

    const uint32_t QHI = su, QLO = su + 8192;
    const uint32_t STG = su + 16384;

#pragma unroll
    for (int i = 0; i < 4; i++) {
        int c = tid + i * 128;             // 0..511
        int r = c >> 3, ch = c & 7;
        uint32_t so = (uint32_t)(r * 128 + (((ch ^ (r & 7)) & 7) << 4));
        const size_t g = (rowbase + q0 + r) * D_ + col0 + ch * 8;
        cp16(QHI + so, Qhi + g);
        cp16(QLO + so, Qlo + g);
    }
    cp_commit();
    att_load_kv(STG, Khi, Klo, Vhi, Vlo, rowbase, 0, col0, tid);
    cp_commit();
    att_load_kv(STG + ATT_STAGE, Khi, Klo, Vhi, Vlo, rowbase, 64, col0, tid);
    cp_commit();

    asm volatile("cp.async.wait_group 2;\n" ::: "memory");
    __syncthreads();

    uint32_t qh[4][4], ql[4][4];
#pragma unroll
    for (int kc = 0; kc < 4; kc++) {
        ldsm_x4(qh[kc], ldsm_addr(QHI, warp * 16, kc * 2, lane));
        ldsm_x4(ql[kc], ldsm_addr(QLO, warp * 16, kc * 2, lane));
    }

    float oacc[8][4];
#pragma unroll
    for (int j = 0; j < 8; j++)
#pragma unroll
        for (int i = 0; i < 4; i++) oacc[j][i] = 0.0f;
    float m0 = -3.0e38f, m1 = -3.0e38f, l0 = 0.0f, l1 = 0.0f;

    for (int c = 0; c < NKV; c++) {
        if (c < NKV - 1)
            asm volatile("cp.async.wait_group 1;\n" ::: "memory");
        else
            asm volatile("cp.async.wait_group 0;\n" ::: "memory");
        __syncthreads();

        const uint32_t KB = STG + (uint32_t)(c & 1) * ATT_STAGE;

        // ---- S = Q @ K^T  (3-term split), S tile [16 q, 64 kv] per warp
        float sacc[8][4];
#pragma unroll
        for (int j = 0; j < 8; j++)
#pragma unroll
            for (int i = 0; i < 4; i++) sacc[j][i] = 0.0f;

#pragma unroll
        for (int kc = 0; kc < 4; kc++) {
            uint32_t kh[4][4], kl[4][4];
#pragma unroll
            for (int ng = 0; ng < 4; ng++) {
                ldsm_x4(kh[ng], ldsm_addr(KB + 0,    ng * 16, kc * 2, lane));
                ldsm_x4(kl[ng], ldsm_addr(KB + 8192, ng * 16, kc * 2, lane));
            }
#pragma unroll
            for (int j = 0; j < 8; j++) {
                const int g = j >> 1, p = j & 1;
                mma_bf16(sacc[j], qh[kc], kh[g][p], kh[g][p + 2]);
                mma_bf16(sacc[j], qh[kc], kl[g][p], kl[g][p + 2]);
                mma_bf16(sacc[j], ql[kc], kh[g][p], kh[g][p + 2]);
            }
        }

        // ---- online softmax in registers (rows lane>>2 and +8)
#pragma unroll
        for (int j = 0; j < 8; j++)
#pragma unroll
            for (int i = 0; i < 4; i++) sacc[j][i] *= 0.125f;

        float mx0 = -3.0e38f, mx1 = -3.0e38f;
#pragma unroll
        for (int j = 0; j < 8; j++) {
            mx0 = fmaxf(mx0, fmaxf(sacc[j][0], sacc[j][1]));
            mx1 = fmaxf(mx1, fmaxf(sacc[j][2], sacc[j][3]));
        }
        mx0 = fmaxf(mx0, __shfl_xor_sync(0xffffffffu, mx0, 1));
        mx0 = fmaxf(mx0, __shfl_xor_sync(0xffffffffu, mx0, 2));
        mx1 = fmaxf(mx1, __shfl_xor_sync(0xffffffffu, mx1, 1));
        mx1 = fmaxf(mx1, __shfl_xor_sync(0xffffffffu, mx1, 2));

        float mn0 = fmaxf(m0, mx0), mn1 = fmaxf(m1, mx1);
        float corr0 = __expf(m0 - mn0), corr1 = __expf(m1 - mn1);
        m0 = mn0; m1 = mn1;

        float s0 = 0.0f, s1 = 0.0f;
#pragma unroll
        for (int j = 0; j < 8; j++) {
            sacc[j][0] = __expf(sacc[j][0] - mn0);
            sacc[j][1] = __expf(sacc[j][1] - mn0);
            sacc[j][2] = __expf(sacc[j][2] - mn1);
            sacc[j][3] = __expf(sacc[j][3] - mn1);
            s0 += sacc[j][0] + sacc[j][1];
            s1 += sacc[j][2] + sacc[j][3];
        }
        s0 += __shfl_xor_sync(0xffffffffu, s0, 1);
        s0 += __shfl_xor_sync(0xffffffffu, s0, 2);
        s1 += __shfl_xor_sync(0xffffffffu, s1, 1);
        s1 += __shfl_xor_sync(0xffffffffu, s1, 2);
        l0 = l0 * corr0 + s0;
        l1 = l1 * corr1 + s1;

#pragma unroll
        for (int j = 0; j < 8; j++) {
            oacc[j][0] *= corr0; oacc[j][1] *= corr0;
            oacc[j][2] *= corr1; oacc[j][3] *= corr1;
        }

        // ---- O += (Phi+Plo) @ (Vhi+Vlo) minus Plo*Vlo cross term
#pragma unroll
        for (int kc = 0; kc < 4; kc++) {
            uint32_t ph[4], pl[4];
            pk_split2(sacc[2 * kc][0],     sacc[2 * kc][1],     ph[0], pl[0]);
            pk_split2(sacc[2 * kc][2],     sacc[2 * kc][3],     ph[1], pl[1]);
            pk_split2(sacc[2 * kc + 1][0], sacc[2 * kc + 1][1], ph[2], pl[2]);
            pk_split2(sacc[2 * kc + 1][2], sacc[2 * kc + 1][3], ph[3], pl[3]);
#pragma unroll
            for (int dg = 0; dg < 4; dg++) {
                uint32_t vh[4], vl[4];
                ldsm_x4_t(vh, ldsm_addr(KB + 16384, kc * 16, dg * 2, lane));
                ldsm_x4_t(vl, ldsm_addr(KB + 24576, kc * 16, dg * 2, lane));
                mma_bf16(oacc[2 * dg],     ph, vh[0], vh[1]);
                mma_bf16(oacc[2 * dg + 1], ph, vh[2], vh[3]);
                mma_bf16(oacc[2 * dg],     ph, vl[0], vl[1]);
                mma_bf16(oacc[2 * dg + 1], ph, vl[2], vl[3]);
                mma_bf16(oacc[2 * dg],     pl, vh[0], vh[1]);
                mma_bf16(oacc[2 * dg + 1], pl, vh[2], vh[3]);
            }
        }

        __syncthreads();
        if (c + 2 < NKV) {
            att_load_kv(STG + (uint32_t)(c & 1) * ATT_STAGE,
                        Khi, Klo, Vhi, Vlo, rowbase, (c + 2) * 64, col0, tid);
            cp_commit();
        }
    }

    // ---- epilogue: normalize, split to bf16 hi/lo, store
    const float inv0 = 1.0f / l0, inv1 = 1.0f / l1;
    const int r0 = warp * 16 + (lane >> 2);
    const int c0 = (lane & 3) * 2;
#pragma unroll
    for (int j = 0; j < 8; j++) {
        const int dcol = col0 + j * 8 + c0;
        const size_t o0 = (rowbase + q0 + r0) * D_ + dcol;
        const size_t o1 = (rowbase + q0 + r0 + 8) * D_ + dcol;
        uint32_t h01, l01, h23, l23;
        pk_split2(oacc[j][0] * inv0, oacc[j][1] * inv0, h01, l01);
        pk_split2(oacc[j][2] * inv1, oacc[j][3] * inv1, h23, l23);
        *(uint32_t*)(Ohi + o0) = h01;
        *(uint32_t*)(Ohi + o1) = h23;
        *(uint32_t*)(Olo + o0) = l01;
        *(uint32_t*)(Olo + o1) = l23;
    }
}

// ---------------------------------------------------------------------------
// kernel_launch: 5 launches total
// ---------------------------------------------------------------------------
extern "C" void kernel_launch(void* const* d_in, const int* in_sizes, int n_in,
                              void* d_out, int out_size)
{
    const float* q  = (const float*)d_in[0];
    const float* k  = (const float*)d_in[1];
    const float* v  = (const float*)d_in[2];
    const float* wq = (const float*)d_in[3];
    const float* bq = (const float*)d_in[4];
    const float* wk = (const float*)d_in[5];
    const float* bk = (const float*)d_in[6];
    const float* wv = (const float*)d_in[7];
    const float* bv = (const float*)d_in[8];
    const float* wo = (const float*)d_in[9];
    const float* bo = (const float*)d_in[10];
    float* out = (float*)d_out;

    __nv_bfloat16 *Xqh, *Xql, *Xkh, *Xkl, *Xvh, *Xvl;
    __nv_bfloat16 *WQh, *WQl, *WKh, *WKl, *WVh, *WVl, *WOh, *WOl;
    __nv_bfloat16 *Qh, *Ql, *Kh, *Kl, *Vh, *Vl;
    cudaGetSymbolAddress((void**)&Xqh, g_Xqhi);
    cudaGetSymbolAddress((void**)&Xql, g_Xqlo);
    cudaGetSymbolAddress((void**)&Xkh, g_Xkhi);
    cudaGetSymbolAddress((void**)&Xkl, g_Xklo);
    cudaGetSymbolAddress((void**)&Xvh, g_Xvhi);
    cudaGetSymbolAddress((void**)&Xvl, g_Xvlo);
    cudaGetSymbolAddress((void**)&WQh, g_WQhi);
    cudaGetSymbolAddress((void**)&WQl, g_WQlo);
    cudaGetSymbolAddress((void**)&WKh, g_WKhi);
    cudaGetSymbolAddress((void**)&WKl, g_WKlo);
    cudaGetSymbolAddress((void**)&WVh, g_WVhi);
    cudaGetSymbolAddress((void**)&WVl, g_WVlo);
    cudaGetSymbolAddress((void**)&WOh, g_WOhi);
    cudaGetSymbolAddress((void**)&WOl, g_WOlo);
    cudaGetSymbolAddress((void**)&Qh, g_Qhi);
    cudaGetSymbolAddress((void**)&Ql, g_Qlo);
    cudaGetSymbolAddress((void**)&Kh, g_Khi);
    cudaGetSymbolAddress((void**)&Kl, g_Klo);
    cudaGetSymbolAddress((void**)&Vh, g_Vhi);
    cudaGetSymbolAddress((void**)&Vl, g_Vlo);

    cudaFuncSetAttribute(gemm_hmma,
                         cudaFuncAttributeMaxDynamicSharedMemorySize, GSMEM);
    cudaFuncSetAttribute(attn_hmma,
                         cudaFuncAttributeMaxDynamicSharedMemorySize, ATT_SMEM);

    // 1) all weight transposes
    TS4 ts = {{wq, wk, wv, wo}, {WQh, WKh, WVh, WOh}, {WQl, WKl, WVl, WOl}};
    transpose_split4_kernel<<<dim3(D_ / 32, D_ / 32, 4), dim3(32, 8)>>>(ts);

    // 2) all input splits
    const int n4 = M_ * D_ / 4;
    SP3 sp = {{q, k, v}, {Xqh, Xkh, Xvh}, {Xql, Xkl, Xvl}};
    split3_kernel<<<dim3(n4 / 256, 1, 3), 256>>>(sp, n4);

    // 3) batched Q/K/V projections (bf16 hi/lo out)
    GBatch pb;
    pb.g[0] = {Xqh, Xql, WQh, WQl, bq, nullptr, Qh, Ql};
    pb.g[1] = {Xkh, Xkl, WKh, WKl, bk, nullptr, Kh, Kl};
    pb.g[2] = {Xvh, Xvl, WVh, WVl, bv, nullptr, Vh, Vl};
    gemm_hmma<<<dim3(D_ / 128, M_ / 128, 3), 256, GSMEM>>>(pb);

    // 4) attention -> O split into Xq buffers (done with their input role)
    attn_hmma<<<dim3(S_ / 64, H_, B_), 128, ATT_SMEM>>>(
        Qh, Ql, Kh, Kl, Vh, Vl, Xqh, Xql);

    // 5) output projection -> fp32 out
    GBatch ob;
    ob.g[0] = {Xqh, Xql, WOh, WOl, bo, out, nullptr, nullptr};
    ob.g[1] = ob.g[0];
    ob.g[2] = ob.g[0];
    gemm_hmma<<<dim3(D_ / 128, M_ / 128, 1), 256, GSMEM>>>(ob);
}